// round 10
// baseline (speedup 1.0000x reference)
#include <cuda_runtime.h>
#include <math.h>

// BinEmbedding: out[p] = emb_table[tok(x[p])]
//   tok = 0 if isnan(x), else clamp(count(bins <= x) - 1, 0) + 1
//
// x (B*L,) f32, bins (256,) f32, emb_table (257*64,) f32,
// out (B*L, 64) f32 = 268 MB written. Confirmed floor: HBM write drain /
// LTS cap (~6.3 TB/s wall-clock); all tile/store/MLP axes converge at 43 us.
//
// R10: last untried lever — Blackwell 256-bit stores (st.global.cs.v8.f32)
// to halve STG count and L1 store-side tag traffic. Each thread owns 32B
// chunks (warp = 1024B contiguous). Rest = converged R7 config.

#define NUM_BINS 256
#define F4_PER_ROW 16                    // 64 floats / 4
#define F8_PER_ROW 8                     // 64 floats / 8 (32B chunks)
#define THREADS 256
#define PPB 256                          // positions per block
#define ITERS (PPB * F8_PER_ROW / THREADS)   // 8 chunks per thread

__device__ __forceinline__ void stg256_cs(void* p, float4 a, float4 b) {
    asm volatile(
        "st.global.cs.v8.f32 [%0], {%1,%2,%3,%4,%5,%6,%7,%8};"
        :: "l"(p),
           "f"(a.x), "f"(a.y), "f"(a.z), "f"(a.w),
           "f"(b.x), "f"(b.y), "f"(b.z), "f"(b.w)
        : "memory");
}

__global__ __launch_bounds__(THREADS) void bin_embed_kernel(
    const float*  __restrict__ x,
    const float*  __restrict__ bins,
    const float4* __restrict__ emb4,     // (NUM_BINS+1) * 16 float4
    float*        __restrict__ out)      // n_pos * 64 floats
{
    __shared__ float sbins[NUM_BINS];
    __shared__ int   stok[PPB];

    const int tid  = threadIdx.x;
    const int base = blockIdx.x * PPB;

    sbins[tid] = bins[tid];              // THREADS == NUM_BINS
    __syncthreads();

    // ---- Phase 1: one search per thread ----
    {
        float v = __ldg(&x[base + tid]);
        int c = 0;
        bool nn = isnan(v);
        #pragma unroll
        for (int s = NUM_BINS >> 1; s > 0; s >>= 1) {
            if (sbins[c + s - 1] <= v) c += s;
        }
        int i0 = c - 1; if (i0 < 0) i0 = 0;
        stok[tid] = nn ? 0 : i0 + 1;
    }
    __syncthreads();

    // ---- Phase 2: gather + 256-bit coalesced streaming stores ----
    // 32B chunk index = tid + k*THREADS; sub8 = tid & 7 invariant;
    // row = (tid>>3) + k*32. Warp stores 1024B contiguous per step.
    const int sub8 = tid & 7;
    int row        = tid >> 3;
    char* outp     = (char*)out + ((size_t)base * F4_PER_ROW + tid) * 32 / 2;
    // NOTE: chunk byte offset = (base*F8_PER_ROW + tid + k*THREADS) * 32
    outp = (char*)out + ((size_t)base * F8_PER_ROW + tid) * 32;

    int tok[ITERS];
    #pragma unroll
    for (int k = 0; k < ITERS; k++) tok[k] = stok[row + k * 32];

    float4 va[ITERS], vb[ITERS];
    #pragma unroll
    for (int k = 0; k < ITERS; k++) {
        const float4* r = &emb4[tok[k] * F4_PER_ROW + sub8 * 2];
        va[k] = __ldg(r);
        vb[k] = __ldg(r + 1);
    }

    #pragma unroll
    for (int k = 0; k < ITERS; k++)
        stg256_cs(outp + (size_t)k * THREADS * 32, va[k], vb[k]);
}

extern "C" void kernel_launch(void* const* d_in, const int* in_sizes, int n_in,
                              void* d_out, int out_size)
{
    const float*  x    = (const float*)d_in[0];
    const float*  bins = (const float*)d_in[1];
    const float4* emb4 = (const float4*)d_in[2];
    float* out = (float*)d_out;

    int n_pos  = in_sizes[0];            // 1,048,576; divisible by PPB
    int blocks = n_pos / PPB;            // 4096

    bin_embed_kernel<<<blocks, THREADS>>>(x, bins, emb4, out);
}